// round 10
// baseline (speedup 1.0000x reference)
#include <cuda_runtime.h>
#include <stdint.h>

// Problem shape (fixed by the dataset): B=1, N=100000, E=3200000, H=8, D=64
#define NN 100000
#define HH 8
#define DD 64
#define EE 3200000
#define TOT (EE*HH)          // 25,600,000 outputs
#define NWORDS (TOT/32)      // 800,000 packed mask words

#define GRIDP 1184           // persistent grids: 8 CTAs/SM * 148 SM
#define DOTS_UN 8

// Scratch (static device arrays). 16B-aligned.
__device__ __align__(16) float    g_a_self[NN*HH];
__device__ __align__(16) float    g_a_adjc[NN*HH];
__device__ __align__(16) unsigned g_M[NN*HH];      // order-encoded per-(target,head) max
__device__ __align__(16) float    g_AQ[NN*HH*2];   // interleaved (a_self, Q) per (node,head)
__device__ __align__(16) unsigned g_mask[NWORDS];  // packed keep bits (bit = j%32, j=e*8+h)

// ---------------------------------------------------------------------------
// Threefry-2x32 (20 rounds), key=(0,42), ctr=(0,j), JAX partitionable:
//   bits(j) = x0 ^ x1 ;  keep(j) = bit31 == 0.
// Adds forced onto the IMAD (fma) pipe via mad.lo.u32 with opaque 'one'.
// ---------------------------------------------------------------------------
__device__ __forceinline__ unsigned addm(unsigned a, unsigned one, unsigned b) {
  unsigned d;
  asm("mad.lo.u32 %0, %1, %2, %3;" : "=r"(d) : "r"(a), "r"(one), "r"(b));
  return d;
}
__device__ __forceinline__ unsigned tf_xor(unsigned j, unsigned one) {
  const unsigned K1  = 42u;
  const unsigned KS2 = 0x1BD11BDAu ^ 42u;
  unsigned x0 = 0u;                 // c0(=0) + ks0(=0)
  unsigned x1 = addm(j, one, K1);   // c1 + ks1
#define TF_R(r) { x0 = addm(x1, one, x0); x1 = __funnelshift_l(x1, x1, (r)); x1 ^= x0; }
  TF_R(13) TF_R(15) TF_R(26) TF_R(6)
  x0 = addm(one, K1, x0);   x1 = addm(one, KS2 + 1u, x1);
  TF_R(17) TF_R(29) TF_R(16) TF_R(24)
  x0 = addm(one, KS2, x0);  x1 = addm(one, 2u, x1);
  TF_R(13) TF_R(15) TF_R(26) TF_R(6)
  /* ks0 = 0 */             x1 = addm(one, K1 + 3u, x1);
  TF_R(17) TF_R(29) TF_R(16) TF_R(24)
  x0 = addm(one, K1, x0);   x1 = addm(one, KS2 + 4u, x1);
  TF_R(13) TF_R(15) TF_R(26) TF_R(6)
  x0 = addm(one, KS2, x0);  x1 = addm(one, 5u, x1);
#undef TF_R
  return x0 ^ x1;
}

// Order-preserving float<->uint encoding for atomicMax
__device__ __forceinline__ unsigned enc_f(float f) {
  unsigned u = __float_as_uint(f);
  return (u & 0x80000000u) ? ~u : (u | 0x80000000u);
}
__device__ __forceinline__ float dec_f(unsigned k) {
  unsigned u = (k & 0x80000000u) ? (k ^ 0x80000000u) : ~k;
  return __uint_as_float(u);
}
__device__ __forceinline__ float leaky(float x) {
  return fmaxf(x, 0.2f * x);
}

// ---------------------------------------------------------------------------
// K1: dots (einsum 'nhd,dh->nh') + g_M zero-init. Warp per head, 8-node unroll.
// ---------------------------------------------------------------------------
__global__ void k_dots(const float* __restrict__ X,
                       const float* __restrict__ Ws,
                       const float* __restrict__ Wa) {
  int w = threadIdx.x >> 5;   // head
  int l = threadIdx.x & 31;
  float ws0 = Ws[(2*l    ) * HH + w];
  float ws1 = Ws[(2*l + 1) * HH + w];
  float wa0 = Wa[(2*l    ) * HH + w];
  float wa1 = Wa[(2*l + 1) * HH + w];

  int n0 = blockIdx.x * DOTS_UN;
  for (; n0 + DOTS_UN <= NN; n0 += GRIDP * DOTS_UN) {
    float2 x[DOTS_UN];
#pragma unroll
    for (int u = 0; u < DOTS_UN; u++)
      x[u] = *reinterpret_cast<const float2*>(
          X + ((size_t)(n0 + u) * HH + w) * DD + 2*l);
    float ds[DOTS_UN], da[DOTS_UN];
#pragma unroll
    for (int u = 0; u < DOTS_UN; u++) {
      ds[u] = x[u].x * ws0 + x[u].y * ws1;
      da[u] = x[u].x * wa0 + x[u].y * wa1;
    }
#pragma unroll
    for (int o = 16; o; o >>= 1)
#pragma unroll
      for (int u = 0; u < DOTS_UN; u++) {
        ds[u] += __shfl_down_sync(0xFFFFFFFFu, ds[u], o);
        da[u] += __shfl_down_sync(0xFFFFFFFFu, da[u], o);
      }
    if (l == 0)
#pragma unroll
      for (int u = 0; u < DOTS_UN; u++) {
        g_a_self[(n0 + u)*HH + w] = ds[u];
        g_a_adjc[(n0 + u)*HH + w] = da[u];
      }
    if (w == 0 && l < 8) {
#pragma unroll
      for (int u = 0; u < DOTS_UN; u++)
        g_M[(n0 + u)*8 + l] = 0u;
    }
  }
  for (; n0 < NN; n0++) {   // tail
    float2 x = *reinterpret_cast<const float2*>(
        X + ((size_t)n0 * HH + w) * DD + 2*l);
    float ds = x.x * ws0 + x.y * ws1;
    float da = x.x * wa0 + x.y * wa1;
#pragma unroll
    for (int o = 16; o; o >>= 1) {
      ds += __shfl_down_sync(0xFFFFFFFFu, ds, o);
      da += __shfl_down_sync(0xFFFFFFFFu, da, o);
    }
    if (l == 0) {
      g_a_self[n0*HH + w] = ds;
      g_a_adjc[n0*HH + w] = da;
    }
    if (w == 0 && l < 8) g_M[n0*8 + l] = 0u;
  }
}

// ---------------------------------------------------------------------------
// F2: cooperative segment-max + mask, fused per-LANE.
// Warp-iter handles 4 edges: lane = sub*8 + h, edge e = e0+sub, head h.
// Each lane: scalar gather aa[s,h] + M[t,h], filtered atomicMax (4B), plus its
// own threefry keep-bit for j = e0*8 + lane; ballot -> mask word g_mask[e0/4].
// The 40 alu-ops of threefry fill the warp's own L2-latency stalls.
// Stale M reads are safe: M only grows, so a stale (lower) value can only
// cause a redundant atomic, never skip a needed one.
// ---------------------------------------------------------------------------
__global__ void k_f2(const int* __restrict__ targets,
                     const int* __restrict__ sources,
                     unsigned one) {
  unsigned lane = threadIdx.x & 31u;
  unsigned sub  = lane >> 3;        // edge within quad
  unsigned h    = lane & 7u;        // head
  unsigned gw   = (blockIdx.x * blockDim.x + threadIdx.x) >> 5;
  const unsigned NWARP = GRIDP * 8u;

  for (unsigned e0 = gw * 4u; e0 < (unsigned)EE; e0 += NWARP * 4u) {
    unsigned e = e0 + sub;
    int t = targets[e];
    int s = sources[e];
    float    aav = g_a_adjc[(unsigned)s*8u + h];
    unsigned cur = g_M[(unsigned)t*8u + h];
    unsigned bits = tf_xor(e0*8u + lane, one);   // fills gather stalls
    unsigned v = enc_f(aav);
    if (v > cur) atomicMax(&g_M[(unsigned)t*8u + h], v);
    unsigned word = __ballot_sync(0xFFFFFFFFu, (bits & 0x80000000u) == 0u);
    if (lane == 0) g_mask[e0 >> 2] = word;
  }
}

// ---------------------------------------------------------------------------
// K3: AQ[i] = (a_self[i], 2*exp(-leaky(a_self[i] + dec(M[i])))).
// Nodes with no incoming edge get NaN Q but are never gathered.
// ---------------------------------------------------------------------------
__global__ void k_prep() {
  int i = blockIdx.x * blockDim.x + threadIdx.x;
  if (i >= NN*HH) return;
  float as = g_a_self[i];
  float q  = 2.0f * __expf(-leaky(as + dec_f(g_M[i])));
  *reinterpret_cast<float2*>(g_AQ + 2*i) = make_float2(as, q);
}

// ---------------------------------------------------------------------------
// K4: cooperative output. Warp-iter = 4 edges, lane = sub*8 + h.
//   out[e,h] = keepbit ? Q[t,h] * exp(leaky(a_self[t,h] + a_adjc[s,h])) : 0
// AQ float2 gather (64B/edge, 1 line), aa scalar gather, one broadcast mask
// word per warp, coalesced 128B store.
// ---------------------------------------------------------------------------
__global__ void k_out(const int* __restrict__ targets,
                      const int* __restrict__ sources,
                      float* __restrict__ out) {
  unsigned lane = threadIdx.x & 31u;
  unsigned sub  = lane >> 3;
  unsigned h    = lane & 7u;
  unsigned gw   = (blockIdx.x * blockDim.x + threadIdx.x) >> 5;
  const unsigned NWARP = 2368u * 8u;

  for (unsigned e0 = gw * 4u; e0 < (unsigned)EE; e0 += NWARP * 4u) {
    unsigned e = e0 + sub;
    int t = targets[e];
    int s = sources[e];
    float2 aq = *reinterpret_cast<const float2*>(g_AQ + ((unsigned)t*8u + h)*2u);
    float  aa = g_a_adjc[(unsigned)s*8u + h];
    unsigned word = g_mask[e0 >> 2];
    float val = ((word >> lane) & 1u)
              ? aq.y * __expf(leaky(aq.x + aa)) : 0.0f;
    out[e0*8u + lane] = val;
  }
}

// ---------------------------------------------------------------------------
extern "C" void kernel_launch(void* const* d_in, const int* in_sizes, int n_in,
                              void* d_out, int out_size) {
  const float* X  = (const float*)d_in[0];
  const float* Ws = (const float*)d_in[1];
  const float* Wa = (const float*)d_in[2];
  // input order: X, Wself, Wadjc, [N scalar], targets, sources, degree
  int ti = (n_in >= 6 && in_sizes[3] == 1) ? 4 : 3;
  const int* targets = (const int*)d_in[ti];
  const int* sources = (const int*)d_in[ti + 1];
  float* out = (float*)d_out;

  k_dots<<<GRIDP, 256>>>(X, Ws, Wa);
  k_f2  <<<GRIDP, 256>>>(targets, sources, 1u);
  k_prep<<<(NN*HH + 255) / 256, 256>>>();
  k_out <<<2368, 256>>>(targets, sources, out);
}

// round 11
// speedup vs baseline: 1.3134x; 1.3134x over previous
#include <cuda_runtime.h>
#include <stdint.h>

// Problem shape (fixed by the dataset): B=1, N=100000, E=3200000, H=8, D=64
#define NN 100000
#define HH 8
#define DD 64
#define EE 3200000
#define TOT (EE*HH)          // 25,600,000 outputs
#define NWORDS (TOT/32)      // 800,000 packed mask words

#define GRID2 1184           // F2 total CTAs
#define D2 768               // F2: [0,D2) edge_max, [D2,GRID2) mask (100%)
#define MW2 ((GRID2 - D2) * 8)

#define DOTS_GRID 1184
#define DOTS_UN 4

// Scratch (static device arrays). 16B-aligned for vec I/O.
__device__ __align__(16) float    g_a_self[NN*HH];
__device__ __align__(16) float    g_a_adjc[NN*HH];
__device__ __align__(16) unsigned g_M[NN*HH];     // order-encoded per-(target,head) max
__device__ __align__(16) unsigned g_mask[NWORDS]; // packed keep bits

// ---------------------------------------------------------------------------
// Threefry-2x32 (20 rounds), key=(0,42), ctr=(0,j), JAX partitionable:
//   bits(j) = x0 ^ x1 ;  keep(j) = bit31 == 0.
// Adds forced onto the IMAD (fma) pipe via mad.lo.u32 with opaque 'one' so the
// alu pipe carries only the mandatory SHF+LOP3 (40 warp-ops/eval).
// ---------------------------------------------------------------------------
__device__ __forceinline__ unsigned addm(unsigned a, unsigned one, unsigned b) {
  unsigned d;
  asm("mad.lo.u32 %0, %1, %2, %3;" : "=r"(d) : "r"(a), "r"(one), "r"(b));
  return d;
}
__device__ __forceinline__ unsigned tf_xor(unsigned j, unsigned one) {
  const unsigned K1  = 42u;
  const unsigned KS2 = 0x1BD11BDAu ^ 42u;
  unsigned x0 = 0u;                 // c0(=0) + ks0(=0)
  unsigned x1 = addm(j, one, K1);   // c1 + ks1
#define TF_R(r) { x0 = addm(x1, one, x0); x1 = __funnelshift_l(x1, x1, (r)); x1 ^= x0; }
  TF_R(13) TF_R(15) TF_R(26) TF_R(6)
  x0 = addm(one, K1, x0);   x1 = addm(one, KS2 + 1u, x1);
  TF_R(17) TF_R(29) TF_R(16) TF_R(24)
  x0 = addm(one, KS2, x0);  x1 = addm(one, 2u, x1);
  TF_R(13) TF_R(15) TF_R(26) TF_R(6)
  /* ks0 = 0 */             x1 = addm(one, K1 + 3u, x1);
  TF_R(17) TF_R(29) TF_R(16) TF_R(24)
  x0 = addm(one, K1, x0);   x1 = addm(one, KS2 + 4u, x1);
  TF_R(13) TF_R(15) TF_R(26) TF_R(6)
  x0 = addm(one, KS2, x0);  x1 = addm(one, 5u, x1);
#undef TF_R
  return x0 ^ x1;
}

// Order-preserving float<->uint encoding for atomicMax
__device__ __forceinline__ unsigned enc_f(float f) {
  unsigned u = __float_as_uint(f);
  return (u & 0x80000000u) ? ~u : (u | 0x80000000u);
}
__device__ __forceinline__ float dec_f(unsigned k) {
  unsigned u = (k & 0x80000000u) ? (k ^ 0x80000000u) : ~k;
  return __uint_as_float(u);
}

// ---------------------------------------------------------------------------
// K1: pure dots (einsum 'nhd,dh->nh') + g_M zero-init.
// Warp per head, 4-node unroll (proven R6 config), grid 1184 for residency.
// ---------------------------------------------------------------------------
__global__ void k_dots(const float* __restrict__ X,
                       const float* __restrict__ Ws,
                       const float* __restrict__ Wa) {
  int w = threadIdx.x >> 5;   // head
  int l = threadIdx.x & 31;
  float ws0 = Ws[(2*l    ) * HH + w];
  float ws1 = Ws[(2*l + 1) * HH + w];
  float wa0 = Wa[(2*l    ) * HH + w];
  float wa1 = Wa[(2*l + 1) * HH + w];

  for (int n0 = blockIdx.x * DOTS_UN; n0 < NN; n0 += DOTS_GRID * DOTS_UN) {
    float2 x[DOTS_UN];
    int nv = (n0 + DOTS_UN <= NN) ? DOTS_UN : (NN - n0);
#pragma unroll
    for (int u = 0; u < DOTS_UN; u++)
      if (u < nv)
        x[u] = *reinterpret_cast<const float2*>(
            X + ((size_t)(n0 + u) * HH + w) * DD + 2*l);
    float ds[DOTS_UN], da[DOTS_UN];
#pragma unroll
    for (int u = 0; u < DOTS_UN; u++)
      if (u < nv) {
        ds[u] = x[u].x * ws0 + x[u].y * ws1;
        da[u] = x[u].x * wa0 + x[u].y * wa1;
      }
#pragma unroll
    for (int o = 16; o; o >>= 1)
#pragma unroll
      for (int u = 0; u < DOTS_UN; u++)
        if (u < nv) {
          ds[u] += __shfl_down_sync(0xFFFFFFFFu, ds[u], o);
          da[u] += __shfl_down_sync(0xFFFFFFFFu, da[u], o);
        }
    if (l == 0)
#pragma unroll
      for (int u = 0; u < DOTS_UN; u++)
        if (u < nv) {
          g_a_self[(n0 + u)*HH + w] = ds[u];
          g_a_adjc[(n0 + u)*HH + w] = da[u];
        }
    if (w == 0 && l < 8 * DOTS_UN) {       // fold g_M zero-init
      int u = l >> 3;
      if (u < nv) g_M[(n0 + u)*8 + (l & 7)] = 0u;
    }
  }
}

// ---------------------------------------------------------------------------
// F2: CTA-role split (the one fusion that measured well, R8).
//   bid <  D2 : segment max (filtered atomics)  — L2/latency-bound, low issue
//   bid >= D2 : FULL mask generation            — alu-bound, uses idle slots
// ---------------------------------------------------------------------------
__global__ void k_f2(const int* __restrict__ targets,
                     const int* __restrict__ sources,
                     unsigned one) {
  if (blockIdx.x >= D2) {
    // mask role: 2 words per iteration (2 independent threefry chains/lane)
    unsigned lane  = threadIdx.x & 31u;
    unsigned mwarp = ((blockIdx.x - D2) * 256 + threadIdx.x) >> 5;
    for (unsigned w = 2u*mwarp; w < (unsigned)NWORDS; w += 2u*MW2) {
      unsigned jA = w * 32u + lane;
      unsigned bitsA = tf_xor(jA, one);
      unsigned bitsB = tf_xor(jA + 32u, one);
      unsigned wordA = __ballot_sync(0xFFFFFFFFu, (bitsA & 0x80000000u) == 0u);
      unsigned wordB = __ballot_sync(0xFFFFFFFFu, (bitsB & 0x80000000u) == 0u);
      if (lane == 0)
        *reinterpret_cast<uint2*>(g_mask + w) = make_uint2(wordA, wordB);
    }
    return;
  }
  for (int e = blockIdx.x * 256 + threadIdx.x; e < EE; e += D2 * 256) {
    int t = targets[e];
    int s = sources[e];
    const float4 a0 = *reinterpret_cast<const float4*>(g_a_adjc + s*8);
    const float4 a1 = *reinterpret_cast<const float4*>(g_a_adjc + s*8 + 4);
    const uint4  m0 = *reinterpret_cast<const uint4 *>(g_M + t*8);
    const uint4  m1 = *reinterpret_cast<const uint4 *>(g_M + t*8 + 4);
    unsigned v;
    v = enc_f(a0.x); if (v > m0.x) atomicMax(&g_M[t*8 + 0], v);
    v = enc_f(a0.y); if (v > m0.y) atomicMax(&g_M[t*8 + 1], v);
    v = enc_f(a0.z); if (v > m0.z) atomicMax(&g_M[t*8 + 2], v);
    v = enc_f(a0.w); if (v > m0.w) atomicMax(&g_M[t*8 + 3], v);
    v = enc_f(a1.x); if (v > m1.x) atomicMax(&g_M[t*8 + 4], v);
    v = enc_f(a1.y); if (v > m1.y) atomicMax(&g_M[t*8 + 5], v);
    v = enc_f(a1.z); if (v > m1.z) atomicMax(&g_M[t*8 + 6], v);
    v = enc_f(a1.w); if (v > m1.w) atomicMax(&g_M[t*8 + 7], v);
  }
}

// ---------------------------------------------------------------------------
// K3: out[j] = keepbit(j) ? 2*exp(e - m) : 0    (R8's measured-fast kernel)
//   e = leaky(a_self[t]+a_adjc[s]),  m = leaky(a_self[t]+max),  m2+eps == 1.0f
// 4 outputs per thread; mask from packed words -> memory-bound kernel.
// ---------------------------------------------------------------------------
__device__ __forceinline__ float edge_val(float a_s, float a_a, unsigned menc,
                                          unsigned keep) {
  float x  = a_s + a_a;
  float e  = (x  >= 0.0f) ? x  : 0.2f * x;
  float mx = a_s + dec_f(menc);
  float m  = (mx >= 0.0f) ? mx : 0.2f * mx;
  float v  = __expf(e - m) * 2.0f;
  return keep ? v : 0.0f;
}

__global__ void k_out(const int* __restrict__ targets,
                      const int* __restrict__ sources,
                      float* __restrict__ out) {
  unsigned tI = blockIdx.x * blockDim.x + threadIdx.x;  // 0 .. TOT/4-1
  if (tI >= (unsigned)(TOT/4)) return;
  unsigned j0 = 4u * tI;

  unsigned word = g_mask[j0 >> 5];
  unsigned b = word >> (j0 & 31u);

  int e = (int)(j0 >> 3);
  int h = (int)(j0 & 7u);        // 0 or 4
  int t = targets[e];
  int s = sources[e];
  float4 as = *reinterpret_cast<const float4*>(g_a_self + t*8 + h);
  float4 aa = *reinterpret_cast<const float4*>(g_a_adjc + s*8 + h);
  uint4  me = *reinterpret_cast<const uint4 *>(g_M      + t*8 + h);

  float4 o;
  o.x = edge_val(as.x, aa.x, me.x,  b        & 1u);
  o.y = edge_val(as.y, aa.y, me.y, (b >> 1u) & 1u);
  o.z = edge_val(as.z, aa.z, me.z, (b >> 2u) & 1u);
  o.w = edge_val(as.w, aa.w, me.w, (b >> 3u) & 1u);
  *reinterpret_cast<float4*>(out + j0) = o;
}

// ---------------------------------------------------------------------------
extern "C" void kernel_launch(void* const* d_in, const int* in_sizes, int n_in,
                              void* d_out, int out_size) {
  const float* X  = (const float*)d_in[0];
  const float* Ws = (const float*)d_in[1];
  const float* Wa = (const float*)d_in[2];
  // input order: X, Wself, Wadjc, [N scalar], targets, sources, degree
  int ti = (n_in >= 6 && in_sizes[3] == 1) ? 4 : 3;
  const int* targets = (const int*)d_in[ti];
  const int* sources = (const int*)d_in[ti + 1];
  float* out = (float*)d_out;

  k_dots<<<DOTS_GRID, 256>>>(X, Ws, Wa);
  k_f2  <<<GRID2, 256>>>(targets, sources, 1u);
  k_out <<<(TOT/4 + 255) / 256, 256>>>(targets, sources, out);
}

// round 13
// speedup vs baseline: 1.5102x; 1.1498x over previous
#include <cuda_runtime.h>
#include <stdint.h>

// Problem shape (fixed by the dataset): B=1, N=100000, E=3200000, H=8, D=64
#define NN 100000
#define HH 8
#define DD 64
#define EE 3200000
#define TOT (EE*HH)          // 25,600,000 outputs

#define DOTS_GRID 1184
#define DOTS_UN 4

// Scratch (static device arrays). 16B-aligned for vec I/O.
__device__ __align__(16) float    g_a_self[NN*HH];
__device__ __align__(16) float    g_a_adjc[NN*HH];
__device__ __align__(16) unsigned g_M[NN*HH];    // order-encoded per-(target,head) max
__device__ __align__(16) float    g_P[NN*HH*2];  // packed per (t,half): {as[4], Q[4]}

// ---------------------------------------------------------------------------
// Threefry-2x32 (20 rounds), key=(0,42), ctr=(0,j), JAX partitionable:
//   bits(j) = x0 ^ x1 ;  keep(j) = bit31 == 0.
// Adds forced onto the IMAD (fma) pipe via mad.lo.u32 with opaque 'one' so the
// alu pipe carries only the mandatory SHF+LOP3 (40 warp-ops/eval).
// ---------------------------------------------------------------------------
__device__ __forceinline__ unsigned addm(unsigned a, unsigned one, unsigned b) {
  unsigned d;
  asm("mad.lo.u32 %0, %1, %2, %3;" : "=r"(d) : "r"(a), "r"(one), "r"(b));
  return d;
}
__device__ __forceinline__ unsigned tf_xor(unsigned j, unsigned one) {
  const unsigned K1  = 42u;
  const unsigned KS2 = 0x1BD11BDAu ^ 42u;
  unsigned x0 = 0u;                 // c0(=0) + ks0(=0)
  unsigned x1 = addm(j, one, K1);   // c1 + ks1
#define TF_R(r) { x0 = addm(x1, one, x0); x1 = __funnelshift_l(x1, x1, (r)); x1 ^= x0; }
  TF_R(13) TF_R(15) TF_R(26) TF_R(6)
  x0 = addm(one, K1, x0);   x1 = addm(one, KS2 + 1u, x1);
  TF_R(17) TF_R(29) TF_R(16) TF_R(24)
  x0 = addm(one, KS2, x0);  x1 = addm(one, 2u, x1);
  TF_R(13) TF_R(15) TF_R(26) TF_R(6)
  /* ks0 = 0 */             x1 = addm(one, K1 + 3u, x1);
  TF_R(17) TF_R(29) TF_R(16) TF_R(24)
  x0 = addm(one, K1, x0);   x1 = addm(one, KS2 + 4u, x1);
  TF_R(13) TF_R(15) TF_R(26) TF_R(6)
  x0 = addm(one, KS2, x0);  x1 = addm(one, 5u, x1);
#undef TF_R
  return x0 ^ x1;
}

// Order-preserving float<->uint encoding for atomicMax
__device__ __forceinline__ unsigned enc_f(float f) {
  unsigned u = __float_as_uint(f);
  return (u & 0x80000000u) ? ~u : (u | 0x80000000u);
}
__device__ __forceinline__ float dec_f(unsigned k) {
  unsigned u = (k & 0x80000000u) ? (k ^ 0x80000000u) : ~k;
  return __uint_as_float(u);
}
__device__ __forceinline__ float leaky(float x) {
  return fmaxf(x, 0.2f * x);
}

// ---------------------------------------------------------------------------
// K1: dots via float4 loads. Warp covers TWO adjacent head-rows of one node:
//   lane 0-15  -> head 2p,   feature 4*(l&15)..+3
//   lane 16-31 -> head 2p+1
// One LDG.128/lane = 512B contiguous per warp. 16-lane shfl_down reduction;
// lanes 0 and 16 hold the sums. g_M zero-init folded in.
// CTA-iter covers 2*DOTS_UN nodes: warp w -> node n0 + 2u + (w>>2), pair p=w&3.
// NOTE node stride of X is H*D = 512 floats.
// ---------------------------------------------------------------------------
__global__ void k_dots(const float* __restrict__ X,
                       const float* __restrict__ Ws,
                       const float* __restrict__ Wa) {
  int w  = threadIdx.x >> 5;
  int l  = threadIdx.x & 31;
  int no = w >> 2;                 // node offset within pair-group (0/1)
  int p  = w & 3;                  // head pair
  int hh = 2*p + (l >> 4);         // this lane's head
  int db = (l & 15) * 4;           // feature base

  float ws0 = Ws[(db    )*HH + hh], ws1 = Ws[(db + 1)*HH + hh];
  float ws2 = Ws[(db + 2)*HH + hh], ws3 = Ws[(db + 3)*HH + hh];
  float wa0 = Wa[(db    )*HH + hh], wa1 = Wa[(db + 1)*HH + hh];
  float wa2 = Wa[(db + 2)*HH + hh], wa3 = Wa[(db + 3)*HH + hh];

  const int STRIDE = DOTS_GRID * 2 * DOTS_UN;
  for (int n0 = blockIdx.x * 2 * DOTS_UN; n0 < NN; n0 += STRIDE) {
    float4 x[DOTS_UN];
    int n[DOTS_UN];
#pragma unroll
    for (int u = 0; u < DOTS_UN; u++) {
      n[u] = n0 + 2*u + no;
      if (n[u] < NN)
        x[u] = *reinterpret_cast<const float4*>(
            X + (size_t)n[u]*512 + hh*64 + db);   // FIX: 512 floats/node
    }
#pragma unroll
    for (int u = 0; u < DOTS_UN; u++) {
      if (n[u] < NN) {
        float ds = x[u].x*ws0 + x[u].y*ws1 + x[u].z*ws2 + x[u].w*ws3;
        float da = x[u].x*wa0 + x[u].y*wa1 + x[u].z*wa2 + x[u].w*wa3;
#pragma unroll
        for (int o = 8; o; o >>= 1) {
          ds += __shfl_down_sync(0xFFFFFFFFu, ds, o);
          da += __shfl_down_sync(0xFFFFFFFFu, da, o);
        }
        if ((l & 15) == 0) {       // lanes 0 and 16
          g_a_self[n[u]*HH + hh] = ds;
          g_a_adjc[n[u]*HH + hh] = da;
          g_M[n[u]*HH + hh] = 0u;
        }
      }
    }
  }
}

// ---------------------------------------------------------------------------
// K2: segment max. One thread per edge, filtered atomics. The second float4 of
// each 32B pair sits in the same 128B line -> L1 hit, ~2 miss-wavefronts/edge.
// Stale reads safe: M only grows, so filtering can only add redundant atomics.
// ---------------------------------------------------------------------------
__global__ void k_em(const int* __restrict__ targets,
                     const int* __restrict__ sources) {
  int e = blockIdx.x * blockDim.x + threadIdx.x;
  if (e >= EE) return;
  int t = targets[e];
  int s = sources[e];
  const float4 a0 = *reinterpret_cast<const float4*>(g_a_adjc + s*8);
  const float4 a1 = *reinterpret_cast<const float4*>(g_a_adjc + s*8 + 4);
  const uint4  m0 = *reinterpret_cast<const uint4 *>(g_M + t*8);
  const uint4  m1 = *reinterpret_cast<const uint4 *>(g_M + t*8 + 4);
  unsigned v;
  v = enc_f(a0.x); if (v > m0.x) atomicMax(&g_M[t*8 + 0], v);
  v = enc_f(a0.y); if (v > m0.y) atomicMax(&g_M[t*8 + 1], v);
  v = enc_f(a0.z); if (v > m0.z) atomicMax(&g_M[t*8 + 2], v);
  v = enc_f(a0.w); if (v > m0.w) atomicMax(&g_M[t*8 + 3], v);
  v = enc_f(a1.x); if (v > m1.x) atomicMax(&g_M[t*8 + 4], v);
  v = enc_f(a1.y); if (v > m1.y) atomicMax(&g_M[t*8 + 5], v);
  v = enc_f(a1.z); if (v > m1.z) atomicMax(&g_M[t*8 + 6], v);
  v = enc_f(a1.w); if (v > m1.w) atomicMax(&g_M[t*8 + 7], v);
}

// ---------------------------------------------------------------------------
// K3: pack P[t,half] = {as[h..h+3], Q[h..h+3]},  Q = 2*exp(-leaky(as + max)).
// One thread per (node, half). (Isolated nodes get NaN Q; never gathered.)
// ---------------------------------------------------------------------------
__global__ void k_prep() {
  int i = blockIdx.x * blockDim.x + threadIdx.x;    // over NN*2
  if (i >= NN*2) return;
  int base = i * 4;                                 // into NN*HH arrays
  float4 as = *reinterpret_cast<const float4*>(g_a_self + base);
  uint4  me = *reinterpret_cast<const uint4 *>(g_M     + base);
  float4 q;
  q.x = 2.0f * __expf(-leaky(as.x + dec_f(me.x)));
  q.y = 2.0f * __expf(-leaky(as.y + dec_f(me.y)));
  q.z = 2.0f * __expf(-leaky(as.z + dec_f(me.z)));
  q.w = 2.0f * __expf(-leaky(as.w + dec_f(me.w)));
  *reinterpret_cast<float4*>(g_P + i*8)     = as;
  *reinterpret_cast<float4*>(g_P + i*8 + 4) = q;
}

// ---------------------------------------------------------------------------
// K4: 4 outputs/thread (edge e, heads h..h+3), threefry inline.
//   out[j] = keep(j) ? Q[t,h] * exp(leaky(as[t,h] + aa[s,h])) : 0
// Gathers: P (as4 + Q4 in ONE 128B line -> 1 miss + 1 L1 hit), aa4 (1 miss).
// Threefry alu work interleaves with the gather stalls in the same warp.
// ---------------------------------------------------------------------------
__global__ void k_out(const int* __restrict__ targets,
                      const int* __restrict__ sources,
                      float* __restrict__ out, unsigned one) {
  unsigned tI = blockIdx.x * blockDim.x + threadIdx.x;  // 0 .. TOT/4-1
  if (tI >= (unsigned)(TOT/4)) return;
  unsigned j0   = 4u * tI;
  unsigned e    = tI >> 1;
  unsigned half = tI & 1u;
  unsigned h    = half * 4u;

  int t = targets[e];
  int s = sources[e];
  const float* pb = g_P + ((unsigned)t*2u + half)*8u;
  float4 as = *reinterpret_cast<const float4*>(pb);
  float4 q  = *reinterpret_cast<const float4*>(pb + 4);
  float4 aa = *reinterpret_cast<const float4*>(g_a_adjc + (unsigned)s*8u + h);

  unsigned b0 = tf_xor(j0,      one);
  unsigned b1 = tf_xor(j0 + 1u, one);
  unsigned b2 = tf_xor(j0 + 2u, one);
  unsigned b3 = tf_xor(j0 + 3u, one);

  float4 o;
  o.x = (b0 & 0x80000000u) ? 0.0f : q.x * __expf(leaky(as.x + aa.x));
  o.y = (b1 & 0x80000000u) ? 0.0f : q.y * __expf(leaky(as.y + aa.y));
  o.z = (b2 & 0x80000000u) ? 0.0f : q.z * __expf(leaky(as.z + aa.z));
  o.w = (b3 & 0x80000000u) ? 0.0f : q.w * __expf(leaky(as.w + aa.w));
  *reinterpret_cast<float4*>(out + j0) = o;
}

// ---------------------------------------------------------------------------
extern "C" void kernel_launch(void* const* d_in, const int* in_sizes, int n_in,
                              void* d_out, int out_size) {
  const float* X  = (const float*)d_in[0];
  const float* Ws = (const float*)d_in[1];
  const float* Wa = (const float*)d_in[2];
  // input order: X, Wself, Wadjc, [N scalar], targets, sources, degree
  int ti = (n_in >= 6 && in_sizes[3] == 1) ? 4 : 3;
  const int* targets = (const int*)d_in[ti];
  const int* sources = (const int*)d_in[ti + 1];
  float* out = (float*)d_out;

  k_dots<<<DOTS_GRID, 256>>>(X, Ws, Wa);
  k_em  <<<(EE + 255) / 256, 256>>>(targets, sources);
  k_prep<<<(NN*2 + 255) / 256, 256>>>();
  k_out <<<(TOT/4 + 255) / 256, 256>>>(targets, sources, out, 1u);
}